// round 1
// baseline (speedup 1.0000x reference)
#include <cuda_runtime.h>
#include <math.h>

#define IMG   112
#define CCH   192
#define TILE  28
#define HALO  3
#define HD    (TILE + 2*HALO)      // 34
#define NHP   (HD*HD)              // 1156 halo pixels
#define NTHREADS 512
#define NWARPS   (NTHREADS/32)     // 16
#define F4    (CCH/4)              // 48 float4 per pixel

__global__ __launch_bounds__(NTHREADS)
void spatial_attn_fused(const float* __restrict__ x,
                        const float* __restrict__ w,
                        float* __restrict__ out)
{
    __shared__ float s_avg[NHP];
    __shared__ float s_max[NHP];
    __shared__ float s_att[TILE*TILE];
    __shared__ float s_w[98];

    const int tid  = threadIdx.x;
    const int warp = tid >> 5;
    const int lane = tid & 31;

    if (tid < 98) s_w[tid] = w[tid];

    // block -> (batch, tile_y, tile_x)
    const int TPR = IMG / TILE;              // 4
    int bidx = blockIdx.x;
    int b    = bidx / (TPR*TPR);
    int tr   = bidx % (TPR*TPR);
    int ty0  = (tr / TPR) * TILE;
    int tx0  = (tr % TPR) * TILE;

    const float* xb = x + (size_t)b * IMG * IMG * CCH;

    // ---- Phase 1: per-halo-pixel channel avg & max (one warp per pixel) ----
    for (int p = warp; p < NHP; p += NWARPS) {
        int hy = ty0 + p / HD - HALO;
        int wx = tx0 + p % HD - HALO;
        float s = 0.f, m = 0.f;
        if (hy >= 0 && hy < IMG && wx >= 0 && wx < IMG) {
            const float* px = xb + ((size_t)hy * IMG + wx) * CCH;
            float v0 = px[lane +   0];
            float v1 = px[lane +  32];
            float v2 = px[lane +  64];
            float v3 = px[lane +  96];
            float v4 = px[lane + 128];
            float v5 = px[lane + 160];
            s = (v0 + v1) + (v2 + v3) + (v4 + v5);
            m = fmaxf(fmaxf(fmaxf(v0, v1), fmaxf(v2, v3)), fmaxf(v4, v5));
            #pragma unroll
            for (int o = 16; o > 0; o >>= 1) {
                s += __shfl_xor_sync(0xffffffffu, s, o);
                m  = fmaxf(m, __shfl_xor_sync(0xffffffffu, m, o));
            }
        }
        if (lane == 0) {
            s_avg[p] = s * (1.0f / CCH);
            s_max[p] = m;
        }
    }
    __syncthreads();

    // ---- Phase 2: 7x7 conv (cross-correlation) + sigmoid ----
    for (int t = tid; t < TILE*TILE; t += NTHREADS) {
        int oy = t / TILE, ox = t % TILE;
        float acc = 0.f;
        #pragma unroll
        for (int kh = 0; kh < 7; kh++) {
            #pragma unroll
            for (int kw = 0; kw < 7; kw++) {
                int p = (oy + kh) * HD + (ox + kw);
                float wa = s_w[(kh*7 + kw)*2 + 0];
                float wm = s_w[(kh*7 + kw)*2 + 1];
                acc = fmaf(s_avg[p], wa, acc);
                acc = fmaf(s_max[p], wm, acc);
            }
        }
        s_att[t] = 1.0f / (1.0f + __expf(-acc));
    }
    __syncthreads();

    // ---- Phase 3: out = x * att, float4 vectorized, coalesced ----
    const int total4 = TILE*TILE*F4;         // 37632
    for (int k = tid; k < total4; k += NTHREADS) {
        int pt = k / F4;
        int c4 = k - pt * F4;
        int oy = pt / TILE, ox = pt - oy * TILE;
        size_t gbase = (((size_t)b * IMG + (ty0 + oy)) * IMG + (tx0 + ox)) * CCH + (size_t)c4 * 4;
        float4 v = *reinterpret_cast<const float4*>(x + gbase);
        float a = s_att[pt];
        v.x *= a; v.y *= a; v.z *= a; v.w *= a;
        *reinterpret_cast<float4*>(out + gbase) = v;
    }
}

extern "C" void kernel_launch(void* const* d_in, const int* in_sizes, int n_in,
                              void* d_out, int out_size)
{
    const float* x = (const float*)d_in[0];
    const float* w = (const float*)d_in[1];
    float* out = (float*)d_out;

    const int B = 32;
    const int TPR = IMG / TILE;              // 4
    dim3 grid(B * TPR * TPR);                // 512 blocks
    spatial_attn_fused<<<grid, NTHREADS>>>(x, w, out);
}

// round 2
// speedup vs baseline: 1.2096x; 1.2096x over previous
#include <cuda_runtime.h>
#include <math.h>

#define IMG   112
#define CCH   192
#define TW    28
#define TH    14
#define HALO  3
#define HDW   (TW + 2*HALO)        // 34
#define HDH   (TH + 2*HALO)        // 20
#define NHP   (HDW*HDH)            // 680 halo pixels
#define NTHREADS 256
#define NWARPS   (NTHREADS/32)     // 8
#define F4    (CCH/4)              // 48 float4 per pixel

__global__ __launch_bounds__(NTHREADS, 6)
void spatial_attn_fused(const float* __restrict__ x,
                        const float* __restrict__ w,
                        float* __restrict__ out)
{
    __shared__ float s_avg[NHP];
    __shared__ float s_max[NHP];
    __shared__ float s_att[TW*TH];
    __shared__ float s_w[98];

    const int tid  = threadIdx.x;
    const int warp = tid >> 5;
    const int lane = tid & 31;

    if (tid < 98) s_w[tid] = w[tid];

    // block -> (batch, tile_y, tile_x)
    const int TPX = IMG / TW;                // 4
    const int TPY = IMG / TH;                // 8
    int bidx = blockIdx.x;
    int b    = bidx / (TPX*TPY);
    int tr   = bidx % (TPX*TPY);
    int ty0  = (tr / TPX) * TH;
    int tx0  = (tr % TPX) * TW;

    const float* xb = x + (size_t)b * IMG * IMG * CCH;

    // ---- Phase 1: per-halo-pixel channel avg & max (one warp per pixel) ----
    for (int p = warp; p < NHP; p += NWARPS) {
        int hy = ty0 + p / HDW - HALO;
        int wx = tx0 + p % HDW - HALO;
        float s = 0.f, m = 0.f;
        if (hy >= 0 && hy < IMG && wx >= 0 && wx < IMG) {
            const float* px = xb + ((size_t)hy * IMG + wx) * CCH;
            float v0 = px[lane +   0];
            float v1 = px[lane +  32];
            float v2 = px[lane +  64];
            float v3 = px[lane +  96];
            float v4 = px[lane + 128];
            float v5 = px[lane + 160];
            s = (v0 + v1) + (v2 + v3) + (v4 + v5);
            m = fmaxf(fmaxf(fmaxf(v0, v1), fmaxf(v2, v3)), fmaxf(v4, v5));
            #pragma unroll
            for (int o = 16; o > 0; o >>= 1) {
                s += __shfl_xor_sync(0xffffffffu, s, o);
                m  = fmaxf(m, __shfl_xor_sync(0xffffffffu, m, o));
            }
        }
        if (lane == 0) {
            s_avg[p] = s * (1.0f / CCH);
            s_max[p] = m;
        }
    }
    __syncthreads();

    // ---- Phase 2: 7x7 conv (cross-correlation) + sigmoid ----
    for (int t = tid; t < TW*TH; t += NTHREADS) {
        int oy = t / TW, ox = t % TW;
        float acc = 0.f;
        #pragma unroll
        for (int kh = 0; kh < 7; kh++) {
            #pragma unroll
            for (int kw = 0; kw < 7; kw++) {
                int p = (oy + kh) * HDW + (ox + kw);
                acc = fmaf(s_avg[p], s_w[(kh*7 + kw)*2 + 0], acc);
                acc = fmaf(s_max[p], s_w[(kh*7 + kw)*2 + 1], acc);
            }
        }
        s_att[t] = 1.0f / (1.0f + __expf(-acc));
    }
    __syncthreads();

    // ---- Phase 3: out = x * att, float4 vectorized, coalesced ----
    const int total4 = TW*TH*F4;             // 18816
    for (int k = tid; k < total4; k += NTHREADS) {
        int pt = k / F4;
        int c4 = k - pt * F4;
        int oy = pt / TW, ox = pt - oy * TW;
        size_t gbase = (((size_t)b * IMG + (ty0 + oy)) * IMG + (tx0 + ox)) * CCH + (size_t)c4 * 4;
        float4 v = *reinterpret_cast<const float4*>(x + gbase);
        float a = s_att[pt];
        v.x *= a; v.y *= a; v.z *= a; v.w *= a;
        *reinterpret_cast<float4*>(out + gbase) = v;
    }
}

extern "C" void kernel_launch(void* const* d_in, const int* in_sizes, int n_in,
                              void* d_out, int out_size)
{
    const float* x = (const float*)d_in[0];
    const float* w = (const float*)d_in[1];
    float* out = (float*)d_out;

    const int TPX = IMG / TW;                // 4
    const int TPY = IMG / TH;                // 8
    dim3 grid(32 * TPX * TPY);               // 1024 blocks
    spatial_attn_fused<<<grid, NTHREADS>>>(x, w, out);
}

// round 4
// speedup vs baseline: 1.6591x; 1.3716x over previous
#include <cuda_runtime.h>
#include <math.h>

#define IMG   112
#define CCH   192
#define NPIX  (32*IMG*IMG)         // 401408 pixels
#define TW    28
#define TH    16
#define HALO  3
#define HDW   (TW + 2*HALO)        // 34
#define HDH   (TH + 2*HALO)        // 22
#define NHP   (HDW*HDH)            // 748
#define NT    256
#define NW    (NT/32)              // 8
#define F4    (CCH/4)              // 48

// pooled[pix*2+0]=avg, [pix*2+1]=max  (3.2 MB, L2-resident)
__device__ float g_pooled[NPIX * 2];

// ---------------- Kernel A: channel avg/max reduction ----------------
__global__ __launch_bounds__(NT, 8)
void reduce_kernel(const float* __restrict__ x)
{
    int warp = (blockIdx.x * NW) + (threadIdx.x >> 5);
    int lane = threadIdx.x & 31;
    if (warp >= NPIX) return;

    const float* px = x + (size_t)warp * CCH;
    float v0 = px[lane +   0];
    float v1 = px[lane +  32];
    float v2 = px[lane +  64];
    float v3 = px[lane +  96];
    float v4 = px[lane + 128];
    float v5 = px[lane + 160];
    float s = (v0 + v1) + (v2 + v3) + (v4 + v5);
    float m = fmaxf(fmaxf(fmaxf(v0, v1), fmaxf(v2, v3)), fmaxf(v4, v5));
    #pragma unroll
    for (int o = 16; o > 0; o >>= 1) {
        s += __shfl_xor_sync(0xffffffffu, s, o);
        m  = fmaxf(m, __shfl_xor_sync(0xffffffffu, m, o));
    }
    if (lane == 0) {
        float2 r = make_float2(s * (1.0f / CCH), m);
        *reinterpret_cast<float2*>(&g_pooled[(size_t)warp * 2]) = r;
    }
}

// ---------------- Kernel B: conv + sigmoid + apply ----------------
__global__ __launch_bounds__(NT, 8)
void apply_kernel(const float* __restrict__ x,
                  const float* __restrict__ w,
                  float* __restrict__ out)
{
    __shared__ float s_avg[NHP];
    __shared__ float s_max[NHP];
    __shared__ float s_att[TW*TH];
    __shared__ float s_w[98];

    const int tid = threadIdx.x;
    if (tid < 98) s_w[tid] = w[tid];

    const int TPX = IMG / TW;                // 4
    const int TPY = IMG / TH;                // 7
    int bidx = blockIdx.x;
    int b    = bidx / (TPX*TPY);
    int tr   = bidx % (TPX*TPY);
    int ty0  = (tr / TPX) * TH;
    int tx0  = (tr % TPX) * TW;

    // ---- Phase 1: load pooled halo (tiny, L2-hot) ----
    for (int p = tid; p < NHP; p += NT) {
        int hy = ty0 + p / HDW - HALO;
        int wx = tx0 + p % HDW - HALO;
        float a = 0.f, m = 0.f;
        if (hy >= 0 && hy < IMG && wx >= 0 && wx < IMG) {
            size_t pix = ((size_t)b * IMG + hy) * IMG + wx;
            float2 r = *reinterpret_cast<const float2*>(&g_pooled[pix * 2]);
            a = r.x; m = r.y;
        }
        s_avg[p] = a;
        s_max[p] = m;
    }
    __syncthreads();

    // ---- Phase 2: 7x7 conv (cross-correlation) + sigmoid ----
    for (int t = tid; t < TW*TH; t += NT) {
        int oy = t / TW, ox = t % TW;
        float acc = 0.f;
        #pragma unroll
        for (int kh = 0; kh < 7; kh++) {
            #pragma unroll
            for (int kw = 0; kw < 7; kw++) {
                int p = (oy + kh) * HDW + (ox + kw);
                acc = fmaf(s_avg[p], s_w[(kh*7 + kw)*2 + 0], acc);
                acc = fmaf(s_max[p], s_w[(kh*7 + kw)*2 + 1], acc);
            }
        }
        s_att[t] = 1.0f / (1.0f + __expf(-acc));
    }
    __syncthreads();

    // ---- Phase 3: out = x * att, float4, unroll-4 for MLP ----
    // total4 = 28*16*48 = 21504 = 21 * (NT*4)  -> no remainder, no guards
    const int total4 = TW*TH*F4;
    #pragma unroll 1
    for (int k = tid; k < total4; k += NT*4) {
        float4 v[4]; float a[4]; size_t g[4];
        #pragma unroll
        for (int u = 0; u < 4; u++) {
            int kk = k + u*NT;
            int pt = kk / F4;
            int c4 = kk - pt * F4;
            int oy = pt / TW, ox = pt - oy * TW;
            g[u] = (((size_t)b * IMG + (ty0 + oy)) * IMG + (tx0 + ox)) * CCH + (size_t)c4 * 4;
            v[u] = *reinterpret_cast<const float4*>(x + g[u]);
            a[u] = s_att[pt];
        }
        #pragma unroll
        for (int u = 0; u < 4; u++) {
            float4 r = v[u]; float s = a[u];
            r.x *= s; r.y *= s; r.z *= s; r.w *= s;
            *reinterpret_cast<float4*>(out + g[u]) = r;
        }
    }
}

extern "C" void kernel_launch(void* const* d_in, const int* in_sizes, int n_in,
                              void* d_out, int out_size)
{
    const float* x = (const float*)d_in[0];
    const float* w = (const float*)d_in[1];
    float* out = (float*)d_out;

    // Kernel A: one warp per pixel
    int blocksA = (NPIX + NW - 1) / NW;      // 50176
    reduce_kernel<<<blocksA, NT>>>(x);

    // Kernel B: one block per 28x16 tile
    const int TPX = IMG / TW, TPY = IMG / TH;   // 4, 7
    apply_kernel<<<32 * TPX * TPY, NT>>>(x, w, out);
}

// round 5
// speedup vs baseline: 1.7982x; 1.0838x over previous
#include <cuda_runtime.h>
#include <math.h>

#define IMG   112
#define CCH   192
#define NPIX  (32*IMG*IMG)         // 401408 pixels
#define TW    28
#define TH    8
#define HALO  3
#define HDW   (TW + 2*HALO)        // 34
#define HDH   (TH + 2*HALO)        // 14
#define NHP   (HDW*HDH)            // 476
#define NT    256
#define NW    (NT/32)              // 8
#define F4    (CCH/4)              // 48

// pooled[pix*2+0]=avg, [pix*2+1]=max  (3.2 MB, L2-resident)
__device__ float g_pooled[NPIX * 2];

// ---------------- Kernel A: channel avg/max reduction ----------------
__global__ __launch_bounds__(NT, 8)
void reduce_kernel(const float* __restrict__ x)
{
    int warp = (blockIdx.x * NW) + (threadIdx.x >> 5);
    int lane = threadIdx.x & 31;
    if (warp >= NPIX) return;

    const float4* px4 = reinterpret_cast<const float4*>(x + (size_t)warp * CCH);
    // 48 float4 per pixel: lanes 0-31 take [0,32), lanes 0-15 take [32,48)
    float4 a = __ldcs(px4 + lane);
    float s, m;
    {
        s = (a.x + a.y) + (a.z + a.w);
        m = fmaxf(fmaxf(a.x, a.y), fmaxf(a.z, a.w));
    }
    if (lane < 16) {
        float4 b = __ldcs(px4 + 32 + lane);
        s += (b.x + b.y) + (b.z + b.w);
        m  = fmaxf(m, fmaxf(fmaxf(b.x, b.y), fmaxf(b.z, b.w)));
    }
    #pragma unroll
    for (int o = 16; o > 0; o >>= 1) {
        s += __shfl_xor_sync(0xffffffffu, s, o);
        m  = fmaxf(m, __shfl_xor_sync(0xffffffffu, m, o));
    }
    if (lane == 0) {
        float2 r = make_float2(s * (1.0f / CCH), m);
        *reinterpret_cast<float2*>(&g_pooled[(size_t)warp * 2]) = r;
    }
}

// ---------------- Kernel B: conv + sigmoid + apply ----------------
__global__ __launch_bounds__(NT, 8)
void apply_kernel(const float* __restrict__ x,
                  const float* __restrict__ w,
                  float* __restrict__ out)
{
    __shared__ float s_avg[NHP];
    __shared__ float s_max[NHP];
    __shared__ float s_att[TW*TH];
    __shared__ float s_w[98];

    const int tid = threadIdx.x;
    if (tid < 98) s_w[tid] = w[tid];

    const int TPX = IMG / TW;                // 4
    const int TPY = IMG / TH;                // 14
    int bidx = blockIdx.x;
    int b    = bidx / (TPX*TPY);
    int tr   = bidx % (TPX*TPY);
    int ty0  = (tr / TPX) * TH;
    int tx0  = (tr % TPX) * TW;

    // ---- Phase 1: load pooled halo (tiny, L2-hot) ----
    for (int p = tid; p < NHP; p += NT) {
        int hy = ty0 + p / HDW - HALO;
        int wx = tx0 + p % HDW - HALO;
        float a = 0.f, m = 0.f;
        if (hy >= 0 && hy < IMG && wx >= 0 && wx < IMG) {
            size_t pix = ((size_t)b * IMG + hy) * IMG + wx;
            float2 r = *reinterpret_cast<const float2*>(&g_pooled[pix * 2]);
            a = r.x; m = r.y;
        }
        s_avg[p] = a;
        s_max[p] = m;
    }
    __syncthreads();

    // ---- Phase 2: 7x7 conv (cross-correlation) + sigmoid ----
    if (tid < TW*TH) {
        int oy = tid / TW, ox = tid % TW;
        float acc = 0.f;
        #pragma unroll
        for (int kh = 0; kh < 7; kh++) {
            #pragma unroll
            for (int kw = 0; kw < 7; kw++) {
                int p = (oy + kh) * HDW + (ox + kw);
                acc = fmaf(s_avg[p], s_w[(kh*7 + kw)*2 + 0], acc);
                acc = fmaf(s_max[p], s_w[(kh*7 + kw)*2 + 1], acc);
            }
        }
        s_att[tid] = 1.0f / (1.0f + __expf(-acc));
    }
    __syncthreads();

    // ---- Phase 3: out = x * att, float4 streaming, unroll-2 ----
    // total4 = 28*8*48 = 10752 = 21 * (NT*2) -> no remainder
    const int total4 = TW*TH*F4;
    #pragma unroll 1
    for (int k = tid; k < total4; k += NT*2) {
        float4 v[2]; float a[2]; size_t g[2];
        #pragma unroll
        for (int u = 0; u < 2; u++) {
            int kk = k + u*NT;
            int pt = kk / F4;
            int c4 = kk - pt * F4;
            int oy = pt / TW, ox = pt - oy * TW;
            g[u] = (((size_t)b * IMG + (ty0 + oy)) * IMG + (tx0 + ox)) * CCH + (size_t)c4 * 4;
            v[u] = __ldcs(reinterpret_cast<const float4*>(x + g[u]));
            a[u] = s_att[pt];
        }
        #pragma unroll
        for (int u = 0; u < 2; u++) {
            float4 r = v[u]; float s = a[u];
            r.x *= s; r.y *= s; r.z *= s; r.w *= s;
            __stcs(reinterpret_cast<float4*>(out + g[u]), r);
        }
    }
}

extern "C" void kernel_launch(void* const* d_in, const int* in_sizes, int n_in,
                              void* d_out, int out_size)
{
    const float* x = (const float*)d_in[0];
    const float* w = (const float*)d_in[1];
    float* out = (float*)d_out;

    // Kernel A: one warp per pixel
    int blocksA = (NPIX + NW - 1) / NW;      // 50176
    reduce_kernel<<<blocksA, NT>>>(x);

    // Kernel B: one block per 28x8 tile
    const int TPX = IMG / TW, TPY = IMG / TH;   // 4, 14
    apply_kernel<<<32 * TPX * TPY, NT>>>(x, w, out);
}